// round 1
// baseline (speedup 1.0000x reference)
#include <cuda_runtime.h>
#include <cstdint>

#define N_NODES 200000

// ---------- device scratch (no allocs allowed) ----------
__device__ float4 g_z0[N_NODES];   // [x - mean, 1]
__device__ float4 g_a1[N_NODES];   // A z0   (xyz = g1, w = deg)
__device__ float4 g_a2[N_NODES];   // A g_a1 (xyz = g2, w = d2)
__device__ float4 g_a3[N_NODES];   // A g_a2 (xyz = g3)
__device__ float  g_sum[3];        // column sums of x
__device__ float  g_mat[36];       // [0:9)=Q1 [9:18)=Q2 [18:27)=Q3 [27:30)=u [30:33)=v [33:36)=b3

// ---------- vector reduction to global (sm_90+) ----------
__device__ __forceinline__ void red_add_v4(float4* p, float4 v) {
    asm volatile("red.global.add.v4.f32 [%0], {%1, %2, %3, %4};"
                 :: "l"(p), "f"(v.x), "f"(v.y), "f"(v.z), "f"(v.w)
                 : "memory");
}

// ---------- kernels ----------
__global__ void k_zero() {
    int i = blockIdx.x * blockDim.x + threadIdx.x;
    float4 z = make_float4(0.f, 0.f, 0.f, 0.f);
    if (i < N_NODES) { g_a1[i] = z; g_a2[i] = z; g_a3[i] = z; }
    if (i < 3) g_sum[i] = 0.f;
}

__global__ void k_mean(const float* __restrict__ x) {
    int n = blockIdx.x * blockDim.x + threadIdx.x;
    float a = 0.f, b = 0.f, c = 0.f;
    if (n < N_NODES) { a = x[3*n]; b = x[3*n+1]; c = x[3*n+2]; }
    #pragma unroll
    for (int o = 16; o > 0; o >>= 1) {
        a += __shfl_down_sync(0xffffffffu, a, o);
        b += __shfl_down_sync(0xffffffffu, b, o);
        c += __shfl_down_sync(0xffffffffu, c, o);
    }
    __shared__ float sa[8], sb[8], sc[8];
    int w = threadIdx.x >> 5, l = threadIdx.x & 31;
    if (l == 0) { sa[w] = a; sb[w] = b; sc[w] = c; }
    __syncthreads();
    if (threadIdx.x == 0) {
        float ta = 0.f, tb = 0.f, tc = 0.f;
        #pragma unroll
        for (int i = 0; i < 8; i++) { ta += sa[i]; tb += sb[i]; tc += sc[i]; }
        atomicAdd(&g_sum[0], ta);
        atomicAdd(&g_sum[1], tb);
        atomicAdd(&g_sum[2], tc);
    }
}

__global__ void k_center(const float* __restrict__ x) {
    int n = blockIdx.x * blockDim.x + threadIdx.x;
    if (n >= N_NODES) return;
    const float inv = 1.0f / (float)N_NODES;
    float m0 = g_sum[0] * inv, m1 = g_sum[1] * inv, m2 = g_sum[2] * inv;
    g_z0[n] = make_float4(x[3*n] - m0, x[3*n+1] - m1, x[3*n+2] - m2, 1.0f);
}

// Precompute the collapsed 3x3 matrices / vectors.
// w1 = c1_w2 (50x3), b1 = c1_b2 (50)
// w2 = c2_w2 (50x53), b2 = c2_b2 (50)
// w3 = c3_w2 (3x103), b3 = c3_b2 (3)
__global__ void k_mat(const float* __restrict__ w1, const float* __restrict__ b1,
                      const float* __restrict__ w2, const float* __restrict__ b2,
                      const float* __restrict__ w3, const float* __restrict__ b3) {
    __shared__ float T[3][50];   // T = W3a * W2a  (3x50)
    int tid = threadIdx.x;
    if (tid < 150) {
        int i = tid / 50, k = tid % 50;
        float s = 0.f;
        for (int j = 0; j < 50; j++) s += w3[i*103 + j] * w2[j*53 + k];
        T[i][k] = s;
    }
    __syncthreads();
    if (tid < 9) {                       // Q3 = T * W1
        int i = tid / 3, c = tid % 3;
        float s = 0.f;
        for (int k = 0; k < 50; k++) s += T[i][k] * w1[k*3 + c];
        g_mat[18 + tid] = s;
    } else if (tid < 18) {               // Q2 = W3a*W2b + W3b*W1
        int q = tid - 9; int i = q / 3, c = q % 3;
        float s = 0.f;
        for (int j = 0; j < 50; j++) s += w3[i*103 + j] * w2[j*53 + 50 + c];
        for (int k = 0; k < 50; k++) s += w3[i*103 + 50 + k] * w1[k*3 + c];
        g_mat[9 + q] = s;
    } else if (tid < 27) {               // Q1 = W3c
        int q = tid - 18; int i = q / 3, c = q % 3;
        g_mat[q] = w3[i*103 + 100 + c];
    } else if (tid < 30) {               // u = T * b1
        int i = tid - 27;
        float s = 0.f;
        for (int k = 0; k < 50; k++) s += T[i][k] * b1[k];
        g_mat[27 + i] = s;
    } else if (tid < 33) {               // v = W3a*b2 + W3b*b1
        int i = tid - 30;
        float s = 0.f;
        for (int j = 0; j < 50; j++) s += w3[i*103 + j] * b2[j];
        for (int k = 0; k < 50; k++) s += w3[i*103 + 50 + k] * b1[k];
        g_mat[30 + i] = s;
    } else if (tid < 36) {               // b3
        g_mat[tid] = b3[tid - 33];
    }
}

// One scatter pass: out[dst] += in[src] over all edges. 4 edges / thread.
__global__ void k_scatter(const int* __restrict__ ei, int E,
                          const float4* __restrict__ in, float4* __restrict__ out) {
    int t = blockIdx.x * blockDim.x + threadIdx.x;
    int n4 = E >> 2;
    if (t < n4) {
        int4 s = __ldg((const int4*)ei + t);
        int4 d = __ldg((const int4*)(ei + E) + t);
        float4 v0 = __ldg(&in[s.x]);
        float4 v1 = __ldg(&in[s.y]);
        float4 v2 = __ldg(&in[s.z]);
        float4 v3 = __ldg(&in[s.w]);
        red_add_v4(&out[d.x], v0);
        red_add_v4(&out[d.y], v1);
        red_add_v4(&out[d.z], v2);
        red_add_v4(&out[d.w], v3);
    } else {
        int rem = E & 3;
        int q = t - n4;
        if (q < rem) {
            int e = 4 * n4 + q;
            int s = __ldg(ei + e);
            int d = __ldg(ei + E + e);
            red_add_v4(&out[d], __ldg(&in[s]));
        }
    }
}

__global__ void k_final(const float* __restrict__ x, float* __restrict__ out) {
    int n = blockIdx.x * blockDim.x + threadIdx.x;
    if (n >= N_NODES) return;
    int r = n % 40;
    if (n < 1960 && (r < 14 || (r >= 25 && r < 39))) {
        out[3*n]   = x[3*n];
        out[3*n+1] = x[3*n+1];
        out[3*n+2] = x[3*n+2];
        return;
    }
    float4 a1 = g_a1[n], a2 = g_a2[n], a3 = g_a3[n];
    const float inv = 1.0f / (float)N_NODES;
    #pragma unroll
    for (int c = 0; c < 3; c++) {
        float s = g_mat[33 + c] + g_sum[c] * inv;          // b3 + mean
        s += a1.x * g_mat[c*3 + 0] + a1.y * g_mat[c*3 + 1] + a1.z * g_mat[c*3 + 2];
        s += a2.x * g_mat[9 + c*3 + 0] + a2.y * g_mat[9 + c*3 + 1] + a2.z * g_mat[9 + c*3 + 2];
        s += a3.x * g_mat[18 + c*3 + 0] + a3.y * g_mat[18 + c*3 + 1] + a3.z * g_mat[18 + c*3 + 2];
        s += a2.w * g_mat[27 + c];   // d2 * u
        s += a1.w * g_mat[30 + c];   // deg * v
        out[3*n + c] = s;
    }
}

// ---------- launch ----------
extern "C" void kernel_launch(void* const* d_in, const int* in_sizes, int n_in,
                              void* d_out, int out_size) {
    const float* x   = (const float*)d_in[0];
    const int*   ei  = (const int*)d_in[1];
    // d_in[2] edge_weight: unused by the reference forward
    const float* w1  = (const float*)d_in[5];   // c1_w2
    const float* b1  = (const float*)d_in[6];   // c1_b2
    const float* w2  = (const float*)d_in[9];   // c2_w2
    const float* b2  = (const float*)d_in[10];  // c2_b2
    const float* w3  = (const float*)d_in[13];  // c3_w2
    const float* b3  = (const float*)d_in[14];  // c3_b2
    float* out = (float*)d_out;

    int E = in_sizes[1] / 2;

    float4 *z0p, *a1p, *a2p, *a3p;
    cudaGetSymbolAddress((void**)&z0p, g_z0);
    cudaGetSymbolAddress((void**)&a1p, g_a1);
    cudaGetSymbolAddress((void**)&a2p, g_a2);
    cudaGetSymbolAddress((void**)&a3p, g_a3);

    const int BT = 256;
    int node_grid = (N_NODES + BT - 1) / BT;
    int n_items = (E >> 2) + (E & 3);
    int edge_grid = (n_items + BT - 1) / BT;

    k_zero<<<node_grid, BT>>>();
    k_mat<<<1, 192>>>(w1, b1, w2, b2, w3, b3);
    k_mean<<<node_grid, BT>>>(x);
    k_center<<<node_grid, BT>>>(x);
    k_scatter<<<edge_grid, BT>>>(ei, E, z0p, a1p);
    k_scatter<<<edge_grid, BT>>>(ei, E, a1p, a2p);
    k_scatter<<<edge_grid, BT>>>(ei, E, a2p, a3p);
    k_final<<<node_grid, BT>>>(x, out);
}